// round 1
// baseline (speedup 1.0000x reference)
#include <cuda_runtime.h>

// retinex_synthesis: out = clip(expm1(log1p(ins) + blur(log1p(bg) - log1p(ins))), 0, 1)
// blur = depthwise 31x31 Gaussian (sigma=5), separable: g (x) g.
// Linearity: blur(bg_log) - blur(ins_log) = blur(d), d = bg_log - ins_log.
// K1: horizontal 31-tap on d  -> g_temp   (smem row tiles, 8 outputs/thread)
// K2: vertical 31-tap on temp -> fused epilogue (16 row-outputs/thread/column)

static constexpr int Wd   = 512;
static constexpr int Hd   = 512;
static constexpr int NIMG = 48;                 // B*C = 16*3
static constexpr int NPIX = NIMG * Hd * Wd;     // 12,582,912
static constexpr int NROWS = NIMG * Hd;         // 24,576

__device__ float g_temp[NPIX];                  // 50.3 MB scratch (allowed: __device__ global)

// Normalized 1D Gaussian, sigma=5, 31 taps. Derived in double precision from
// w[j] = exp(-(j-15)^2/50) / sum. Literal constants -> FFMA-imm (rt=1).
#define GW_LIST { \
    8.8805900e-4f, 1.5860940e-3f, 2.7217700e-3f, 4.4874400e-3f, 7.1084370e-3f, \
    1.0818768e-2f, 1.5820117e-2f, 2.2226435e-2f, 3.0002550e-2f, 3.8911210e-2f, \
    4.8486353e-2f, 5.8048703e-2f, 6.6771903e-2f, 7.3794366e-2f, 7.8357554e-2f, \
    7.9940482e-2f, \
    7.8357554e-2f, 7.3794366e-2f, 6.6771903e-2f, 5.8048703e-2f, 4.8486353e-2f, \
    3.8911210e-2f, 3.0002550e-2f, 2.2226435e-2f, 1.5820117e-2f, 1.0818768e-2f, \
    7.1084370e-3f, 4.4874400e-3f, 2.7217700e-3f, 1.5860940e-3f, 8.8805900e-4f }

__device__ __forceinline__ float flog1p(float x) {
    // x in [0,1]; 1+x in [1,2] -> MUFU.LG2 path is plenty accurate here.
    return __logf(1.0f + x);
}

// ---------------------------------------------------------------------------
// K1: horizontal blur of d = log1p(bg) - log1p(ins).
// One block = 4 consecutive rows (rows are contiguous across the whole tensor,
// never straddling an image since each row lies within one (b,c) plane).
// ---------------------------------------------------------------------------
__global__ void __launch_bounds__(256) k_hblur(const float* __restrict__ bg,
                                               const float* __restrict__ ins) {
    const float w[31] = GW_LIST;
    __shared__ __align__(16) float s[4][544];   // 15 zero | 512 data | 17 zero

    const int tid = threadIdx.x;

    // zero the pads: 32 pad slots per row * 4 rows = 128 stores
    if (tid < 128) {
        const int r = tid >> 5, p = tid & 31;
        s[r][(p < 15) ? p : (512 + p)] = 0.0f;  // p=15..31 -> 527..543
    }

    // Each thread loads 8 contiguous floats of bg & ins (block covers 2048 floats).
    const size_t e4 = (size_t)blockIdx.x * 512 + (size_t)tid * 2;  // float4 index
    const float4* bg4 = (const float4*)bg;
    const float4* in4 = (const float4*)ins;
    const float4 b0 = bg4[e4],     b1 = bg4[e4 + 1];
    const float4 i0 = in4[e4],     i1 = in4[e4 + 1];

    const int row = tid >> 6;            // 0..3
    const int col = (tid & 63) * 8;      // 0..504
    float* sp = &s[row][15 + col];
    sp[0] = flog1p(b0.x) - flog1p(i0.x);
    sp[1] = flog1p(b0.y) - flog1p(i0.y);
    sp[2] = flog1p(b0.z) - flog1p(i0.z);
    sp[3] = flog1p(b0.w) - flog1p(i0.w);
    sp[4] = flog1p(b1.x) - flog1p(i1.x);
    sp[5] = flog1p(b1.y) - flog1p(i1.y);
    sp[6] = flog1p(b1.z) - flog1p(i1.z);
    sp[7] = flog1p(b1.w) - flog1p(i1.w);

    __syncthreads();

    // 38-value register window -> 8 outputs. Vectorized LDS.128 (aligned: col%8==0).
    float v[40];
#pragma unroll
    for (int q = 0; q < 10; q++) {
        const float4 t = *(const float4*)&s[row][col + 4 * q];
        v[4*q + 0] = t.x; v[4*q + 1] = t.y; v[4*q + 2] = t.z; v[4*q + 3] = t.w;
    }

    float acc[8];
#pragma unroll
    for (int r = 0; r < 8; r++) acc[r] = 0.0f;
#pragma unroll
    for (int j = 0; j < 38; j++) {
#pragma unroll
        for (int r = 0; r < 8; r++) {
            const int k = j - r;
            if (k >= 0 && k < 31) acc[r] = fmaf(w[k], v[j], acc[r]);
        }
    }

    float4* t4 = (float4*)(g_temp + ((size_t)blockIdx.x * 4 + row) * Wd + col);
    t4[0] = make_float4(acc[0], acc[1], acc[2], acc[3]);
    t4[1] = make_float4(acc[4], acc[5], acc[6], acc[7]);
}

// ---------------------------------------------------------------------------
// K2: vertical blur of g_temp + fused epilogue.
// Thread = one column x, 16 row outputs. grid = (512/256, 512/16, 48).
// ---------------------------------------------------------------------------
__global__ void __launch_bounds__(256) k_vfinal(const float* __restrict__ ins,
                                                float* __restrict__ out) {
    const float w[31] = GW_LIST;
    const int x   = blockIdx.x * 256 + threadIdx.x;
    const int y0  = blockIdx.y * 16;
    const size_t base = (size_t)blockIdx.z * (Hd * Wd) + x;

    float acc[16];
#pragma unroll
    for (int r = 0; r < 16; r++) acc[r] = 0.0f;

#pragma unroll
    for (int m = 0; m < 46; m++) {
        const int yy = y0 + m - 15;
        float v = 0.0f;
        if (yy >= 0 && yy < Hd) v = g_temp[base + (size_t)yy * Wd];
#pragma unroll
        for (int r = 0; r < 16; r++) {
            const int j = m - r;
            if (j >= 0 && j < 31) acc[r] = fmaf(w[j], v, acc[r]);
        }
    }

#pragma unroll
    for (int r = 0; r < 16; r++) {
        const float il = flog1p(ins[base + (size_t)(y0 + r) * Wd]);
        const float L  = il + acc[r];
        const float e  = __expf(L) - 1.0f;          // expm1; abs err ~1e-7, fine
        out[base + (size_t)(y0 + r) * Wd] = fminf(fmaxf(e, 0.0f), 1.0f);
    }
}

// ---------------------------------------------------------------------------
extern "C" void kernel_launch(void* const* d_in, const int* in_sizes, int n_in,
                              void* d_out, int out_size) {
    (void)in_sizes; (void)n_in; (void)out_size;
    const float* bg  = (const float*)d_in[0];   // background
    const float* ins = (const float*)d_in[1];   // insatance
    float* out = (float*)d_out;

    k_hblur <<<NROWS / 4, 256>>>(bg, ins);
    k_vfinal<<<dim3(Wd / 256, Hd / 16, NIMG), 256>>>(ins, out);
}

// round 2
// speedup vs baseline: 1.0443x; 1.0443x over previous
#include <cuda_runtime.h>

// retinex_synthesis: out = clip(expm1(log1p(ins) + blur(log1p(bg) - log1p(ins))), 0, 1)
// blur = depthwise 31x31 Gaussian (sigma=5), separable.
// Algebra:
//   blur(bg_log) - blur(ins_log) = blur(d),   d = log(1+bg) - log(1+ins)
//   work in log2: d2 = log2(1+bg) - log2(1+ins); acc = blur(d2)
//   out = expm1(ln(1+ins) + ln2*acc) = (1+ins) * 2^acc - 1
// K1: horizontal 31-tap on d2 -> g_temp  (aligned smem, STS.128/LDS.128)
// K2: vertical 31-tap, 32 rows/thread, fused epilogue, templated edge guards.

static constexpr int Wd    = 512;
static constexpr int Hd    = 512;
static constexpr int NIMG  = 48;                // B*C = 16*3
static constexpr int NPIX  = NIMG * Hd * Wd;    // 12,582,912
static constexpr int NROWS = NIMG * Hd;         // 24,576

__device__ float g_temp[NPIX];                  // 50.3 MB scratch (__device__ global: allowed)

// Normalized 1D Gaussian, sigma=5, 31 taps (double-derived literals -> FFMA-imm).
#define GW_LIST { \
    8.8805900e-4f, 1.5860940e-3f, 2.7217700e-3f, 4.4874400e-3f, 7.1084370e-3f, \
    1.0818768e-2f, 1.5820117e-2f, 2.2226435e-2f, 3.0002550e-2f, 3.8911210e-2f, \
    4.8486353e-2f, 5.8048703e-2f, 6.6771903e-2f, 7.3794366e-2f, 7.8357554e-2f, \
    7.9940482e-2f, \
    7.8357554e-2f, 7.3794366e-2f, 6.6771903e-2f, 5.8048703e-2f, 4.8486353e-2f, \
    3.8911210e-2f, 3.0002550e-2f, 2.2226435e-2f, 1.5820117e-2f, 1.0818768e-2f, \
    7.1084370e-3f, 4.4874400e-3f, 2.7217700e-3f, 1.5860940e-3f, 8.8805900e-4f }

__device__ __forceinline__ float ex2(float x) {        // MUFU.EX2, flag-independent
    float r; asm("ex2.approx.ftz.f32 %0, %1;" : "=f"(r) : "f"(x)); return r;
}
__device__ __forceinline__ float dlog2(float b, float i) {   // log2(1+b)-log2(1+i)
    return __log2f(1.0f + b) - __log2f(1.0f + i);
}

// ---------------------------------------------------------------------------
// K1: horizontal blur of d2. One block = 4 consecutive rows.
// smem row: [0..15]=0 | data [16..527] | [528..543]=0  -> 16B-aligned vectors.
// ---------------------------------------------------------------------------
__global__ void __launch_bounds__(256) k_hblur(const float* __restrict__ bg,
                                               const float* __restrict__ ins) {
    const float w[31] = GW_LIST;
    __shared__ __align__(16) float s[4][544];

    const int tid = threadIdx.x;
    if (tid < 128) {                                   // zero the 32 pad slots/row
        const int r = tid >> 5, p = tid & 31;
        s[r][(p < 16) ? p : (512 + p)] = 0.0f;
    }

    const size_t e4 = (size_t)blockIdx.x * 512 + (size_t)tid * 2;   // float4 idx
    const float4 b0 = ((const float4*)bg)[e4],  b1 = ((const float4*)bg)[e4 + 1];
    const float4 i0 = ((const float4*)ins)[e4], i1 = ((const float4*)ins)[e4 + 1];

    const int row = tid >> 6;             // 0..3
    const int col = (tid & 63) * 8;       // 0..504
    float4* sp = (float4*)&s[row][16 + col];           // 16B aligned -> STS.128
    sp[0] = make_float4(dlog2(b0.x, i0.x), dlog2(b0.y, i0.y),
                        dlog2(b0.z, i0.z), dlog2(b0.w, i0.w));
    sp[1] = make_float4(dlog2(b1.x, i1.x), dlog2(b1.y, i1.y),
                        dlog2(b1.z, i1.z), dlog2(b1.w, i1.w));

    __syncthreads();

    // 40-value aligned register window (taps j=1..38 used) -> 8 outputs.
    float v[40];
#pragma unroll
    for (int q = 0; q < 10; q++) {
        const float4 t = *(const float4*)&s[row][col + 4 * q];     // LDS.128
        v[4*q + 0] = t.x; v[4*q + 1] = t.y; v[4*q + 2] = t.z; v[4*q + 3] = t.w;
    }

    float acc[8];
#pragma unroll
    for (int r = 0; r < 8; r++) acc[r] = 0.0f;
#pragma unroll
    for (int j = 1; j < 39; j++) {
#pragma unroll
        for (int r = 0; r < 8; r++) {
            const int k = j - 1 - r;
            if (k >= 0 && k < 31) acc[r] = fmaf(w[k], v[j], acc[r]);
        }
    }

    float4* t4 = (float4*)(g_temp + ((size_t)blockIdx.x * 4 + row) * Wd + col);
    t4[0] = make_float4(acc[0], acc[1], acc[2], acc[3]);
    t4[1] = make_float4(acc[4], acc[5], acc[6], acc[7]);
}

// ---------------------------------------------------------------------------
// K2: vertical blur + fused epilogue. Thread = one column x, 32 row outputs.
// GUARD only for the first/last y-block (uniform per-block branch).
// ---------------------------------------------------------------------------
template <bool GUARD>
__device__ __forceinline__ void vbody(const float* __restrict__ ins,
                                      float* __restrict__ out,
                                      int y0, size_t base) {
    const float w[31] = GW_LIST;
    float acc[32];
#pragma unroll
    for (int r = 0; r < 32; r++) acc[r] = 0.0f;

#pragma unroll
    for (int m = 0; m < 62; m++) {
        const int yy = y0 + m - 15;
        float v;
        if (GUARD) v = (yy >= 0 && yy < Hd) ? g_temp[base + (size_t)yy * Wd] : 0.0f;
        else       v = g_temp[base + (size_t)yy * Wd];
#pragma unroll
        for (int r = 0; r < 32; r++) {
            const int k = m - r;
            if (k >= 0 && k < 31) acc[r] = fmaf(w[k], v, acc[r]);
        }
    }

#pragma unroll
    for (int r = 0; r < 32; r++) {
        const float iv = ins[base + (size_t)(y0 + r) * Wd];
        const float e  = fmaf(iv + 1.0f, ex2(acc[r]), -1.0f);   // (1+ins)*2^acc - 1
        out[base + (size_t)(y0 + r) * Wd] = fminf(fmaxf(e, 0.0f), 1.0f);
    }
}

__global__ void __launch_bounds__(256) k_vfinal(const float* __restrict__ ins,
                                                float* __restrict__ out) {
    const int x  = blockIdx.x * 256 + threadIdx.x;
    const int y0 = blockIdx.y * 32;
    const size_t base = (size_t)blockIdx.z * (Hd * Wd) + x;

    if (blockIdx.y == 0 || blockIdx.y == gridDim.y - 1)
        vbody<true >(ins, out, y0, base);
    else
        vbody<false>(ins, out, y0, base);
}

// ---------------------------------------------------------------------------
extern "C" void kernel_launch(void* const* d_in, const int* in_sizes, int n_in,
                              void* d_out, int out_size) {
    (void)in_sizes; (void)n_in; (void)out_size;
    const float* bg  = (const float*)d_in[0];   // background
    const float* ins = (const float*)d_in[1];   // insatance
    float* out = (float*)d_out;

    k_hblur <<<NROWS / 4, 256>>>(bg, ins);
    k_vfinal<<<dim3(Wd / 256, Hd / 32, NIMG), 256>>>(ins, out);
}

// round 3
// speedup vs baseline: 1.1634x; 1.1141x over previous
#include <cuda_runtime.h>
#include <cuda_fp16.h>

// retinex_synthesis: out = clip(expm1(log1p(ins) + blur(log1p(bg) - log1p(ins))), 0, 1)
// blur = depthwise 31x31 Gaussian (sigma=5), separable.
// Algebra:
//   blur(bg_log) - blur(ins_log) = blur(d),   d = log(1+bg) - log(1+ins)
//   work in log2: d2 = log2(1+bg) - log2(1+ins); acc = blur(d2)
//   out = expm1(ln(1+ins) + ln2*acc) = (1+ins) * 2^acc - 1
// K1: horizontal 31-tap on d2 -> g_temp (fp16: halves temp DRAM traffic)
// K2: vertical 31-tap, 32 rows/thread, fused epilogue, templated edge guards.

static constexpr int Wd    = 512;
static constexpr int Hd    = 512;
static constexpr int NIMG  = 48;                // B*C = 16*3
static constexpr int NPIX  = NIMG * Hd * Wd;    // 12,582,912
static constexpr int NROWS = NIMG * Hd;         // 24,576

__device__ __half g_temp[NPIX];                 // 25.2 MB scratch (__device__ global)

// Normalized 1D Gaussian, sigma=5, 31 taps (double-derived literals -> FFMA-imm).
#define GW_LIST { \
    8.8805900e-4f, 1.5860940e-3f, 2.7217700e-3f, 4.4874400e-3f, 7.1084370e-3f, \
    1.0818768e-2f, 1.5820117e-2f, 2.2226435e-2f, 3.0002550e-2f, 3.8911210e-2f, \
    4.8486353e-2f, 5.8048703e-2f, 6.6771903e-2f, 7.3794366e-2f, 7.8357554e-2f, \
    7.9940482e-2f, \
    7.8357554e-2f, 7.3794366e-2f, 6.6771903e-2f, 5.8048703e-2f, 4.8486353e-2f, \
    3.8911210e-2f, 3.0002550e-2f, 2.2226435e-2f, 1.5820117e-2f, 1.0818768e-2f, \
    7.1084370e-3f, 4.4874400e-3f, 2.7217700e-3f, 1.5860940e-3f, 8.8805900e-4f }

__device__ __forceinline__ float ex2(float x) {        // MUFU.EX2
    float r; asm("ex2.approx.ftz.f32 %0, %1;" : "=f"(r) : "f"(x)); return r;
}
__device__ __forceinline__ float dlog2(float b, float i) {   // log2(1+b)-log2(1+i)
    return __log2f(1.0f + b) - __log2f(1.0f + i);
}
__device__ __forceinline__ unsigned h2u(__half2 h) {
    union { __half2 h; unsigned u; } c; c.h = h; return c.u;
}

// ---------------------------------------------------------------------------
// K1: horizontal blur of d2. One block = 4 consecutive rows.
// smem row: [0..15]=0 | data [16..527] | [528..543]=0  -> 16B-aligned vectors.
// ---------------------------------------------------------------------------
__global__ void __launch_bounds__(256) k_hblur(const float* __restrict__ bg,
                                               const float* __restrict__ ins) {
    const float w[31] = GW_LIST;
    __shared__ __align__(16) float s[4][544];

    const int tid = threadIdx.x;
    if (tid < 128) {                                   // zero the 32 pad slots/row
        const int r = tid >> 5, p = tid & 31;
        s[r][(p < 16) ? p : (512 + p)] = 0.0f;
    }

    const size_t e4 = (size_t)blockIdx.x * 512 + (size_t)tid * 2;   // float4 idx
    const float4 b0 = ((const float4*)bg)[e4],  b1 = ((const float4*)bg)[e4 + 1];
    const float4 i0 = ((const float4*)ins)[e4], i1 = ((const float4*)ins)[e4 + 1];

    const int row = tid >> 6;             // 0..3
    const int col = (tid & 63) * 8;       // 0..504
    float4* sp = (float4*)&s[row][16 + col];           // STS.128
    sp[0] = make_float4(dlog2(b0.x, i0.x), dlog2(b0.y, i0.y),
                        dlog2(b0.z, i0.z), dlog2(b0.w, i0.w));
    sp[1] = make_float4(dlog2(b1.x, i1.x), dlog2(b1.y, i1.y),
                        dlog2(b1.z, i1.z), dlog2(b1.w, i1.w));

    __syncthreads();

    // 40-value aligned register window (taps j=1..38 used) -> 8 outputs.
    float v[40];
#pragma unroll
    for (int q = 0; q < 10; q++) {
        const float4 t = *(const float4*)&s[row][col + 4 * q];     // LDS.128
        v[4*q + 0] = t.x; v[4*q + 1] = t.y; v[4*q + 2] = t.z; v[4*q + 3] = t.w;
    }

    float acc[8];
#pragma unroll
    for (int r = 0; r < 8; r++) acc[r] = 0.0f;
#pragma unroll
    for (int j = 1; j < 39; j++) {
#pragma unroll
        for (int r = 0; r < 8; r++) {
            const int k = j - 1 - r;
            if (k >= 0 && k < 31) acc[r] = fmaf(w[k], v[j], acc[r]);
        }
    }

    // Pack 8 fp32 -> 8 fp16 (16 bytes) -> one STG.128
    uint4 u;
    u.x = h2u(__floats2half2_rn(acc[0], acc[1]));
    u.y = h2u(__floats2half2_rn(acc[2], acc[3]));
    u.z = h2u(__floats2half2_rn(acc[4], acc[5]));
    u.w = h2u(__floats2half2_rn(acc[6], acc[7]));
    *(uint4*)(g_temp + ((size_t)blockIdx.x * 4 + row) * Wd + col) = u;
}

// ---------------------------------------------------------------------------
// K2: vertical blur + fused epilogue. Thread = one column x, 32 row outputs.
// GUARD only for the first/last y-block (uniform per-block branch).
// ---------------------------------------------------------------------------
template <bool GUARD>
__device__ __forceinline__ void vbody(const float* __restrict__ ins,
                                      float* __restrict__ out,
                                      int y0, size_t base) {
    const float w[31] = GW_LIST;
    float acc[32];
#pragma unroll
    for (int r = 0; r < 32; r++) acc[r] = 0.0f;

#pragma unroll
    for (int m = 0; m < 62; m++) {
        const int yy = y0 + m - 15;
        float v;
        if (GUARD) v = (yy >= 0 && yy < Hd)
                     ? __half2float(g_temp[base + (size_t)yy * Wd]) : 0.0f;
        else       v = __half2float(g_temp[base + (size_t)yy * Wd]);
#pragma unroll
        for (int r = 0; r < 32; r++) {
            const int k = m - r;
            if (k >= 0 && k < 31) acc[r] = fmaf(w[k], v, acc[r]);
        }
    }

#pragma unroll
    for (int r = 0; r < 32; r++) {
        const float iv = ins[base + (size_t)(y0 + r) * Wd];
        const float e  = fmaf(iv + 1.0f, ex2(acc[r]), -1.0f);   // (1+ins)*2^acc - 1
        out[base + (size_t)(y0 + r) * Wd] = fminf(fmaxf(e, 0.0f), 1.0f);
    }
}

__global__ void __launch_bounds__(256, 4) k_vfinal(const float* __restrict__ ins,
                                                   float* __restrict__ out) {
    const int x  = blockIdx.x * 256 + threadIdx.x;
    const int y0 = blockIdx.y * 32;
    const size_t base = (size_t)blockIdx.z * (Hd * Wd) + x;

    if (blockIdx.y == 0 || blockIdx.y == gridDim.y - 1)
        vbody<true >(ins, out, y0, base);
    else
        vbody<false>(ins, out, y0, base);
}

// ---------------------------------------------------------------------------
extern "C" void kernel_launch(void* const* d_in, const int* in_sizes, int n_in,
                              void* d_out, int out_size) {
    (void)in_sizes; (void)n_in; (void)out_size;
    const float* bg  = (const float*)d_in[0];   // background
    const float* ins = (const float*)d_in[1];   // insatance
    float* out = (float*)d_out;

    k_hblur <<<NROWS / 4, 256>>>(bg, ins);
    k_vfinal<<<dim3(Wd / 256, Hd / 32, NIMG), 256>>>(ins, out);
}